// round 5
// baseline (speedup 1.0000x reference)
#include <cuda_runtime.h>
#include <cuda_bf16.h>
#include <math.h>

// ---------------- problem constants ----------------
#define WSZ 7
#define SHIFT_SZ 3
#define HEADS 16
#define C_DIM 512
#define HD 32
#define NREF 100
#define H_IMG 112
#define NWX 16            // windows per row = 112/7
#define NW_PER 256        // windows per image
#define B_IMG 2
#define NWIN 49           // tokens per window
#define L_IMG 12544       // 112*112
#define NTOK 25088        // B_IMG * L_IMG
#define CONV_H 12544      // NW_PER * NWIN
#define CONV_W 100        // NREF
#define CONV_HW 1254400
#define RA_TOTAL 40140800ll   // 2*16*CONV_HW
#define SCALE_ATT 0.17677669529663687f

// ---------------- scratch (static device globals; no allocation) ----------------
__device__ float g_xw   [(size_t)NTOK * C_DIM];        // LN1 + shifted-window partition
__device__ float g_qkv  [(size_t)NTOK * 3 * C_DIM];    // fused qkv, layout (tok, 3*512)
__device__ float g_refq [B_IMG * HEADS * NREF * HD];
__device__ float g_refv [B_IMG * HEADS * NREF * HD];
__device__ float g_ra   [(size_t)B_IMG * HEADS * CONV_HW];  // conv-layout ra
__device__ float g_u    [(size_t)B_IMG * HEADS * CONV_HW];  // conv output scratch
__device__ double g_stats[64];                              // per-(b,h) sum / sumsq
__device__ float g_qnew [(size_t)NTOK * C_DIM];        // (w,h,n,d)
__device__ float g_attno[(size_t)NTOK * C_DIM];        // attention out (tok, C)
__device__ float g_y    [(size_t)NTOK * C_DIM];        // x + attn (B,L,C)
__device__ float g_h2   [(size_t)NTOK * C_DIM];        // LN2 out
__device__ float g_mlp  [(size_t)NTOK * 4 * C_DIM];    // fc1+gelu out

// ---------------- helpers ----------------
__device__ __forceinline__ float gelu_f(float x) {
    return 0.5f * x * (1.0f + erff(x * 0.70710678118654752f));
}

// token index -> (b, l) row in the original (B, L) layout (shifted-window map)
__device__ __forceinline__ int scat_row(int t) {
    int w  = t / NWIN, n = t % NWIN;
    int bi = w / NW_PER, wl = w % NW_PER;
    int wr = wl / NWX,  wc = wl % NWX;
    int i  = n / WSZ,   j  = n % WSZ;
    int hh = (wr * WSZ + i + SHIFT_SZ) % H_IMG;
    int ww = (wc * WSZ + j + SHIFT_SZ) % H_IMG;
    return bi * L_IMG + hh * H_IMG + ww;
}

// ---------------- LayerNorm (optionally gathering through shifted-window map) ----------------
template <bool GATHER>
__global__ void __launch_bounds__(256) k_ln(const float* __restrict__ in,
                                            const float* __restrict__ w,
                                            const float* __restrict__ b,
                                            float* __restrict__ out) {
    int t   = blockIdx.x;
    int src = GATHER ? scat_row(t) : t;
    const float* row = in + (size_t)src * C_DIM;
    int tid = threadIdx.x;
    float v0 = row[tid], v1 = row[tid + 256];
    float s = v0 + v1, s2 = v0 * v0 + v1 * v1;
    __shared__ float rs[8], rs2[8], stat[2];
    #pragma unroll
    for (int o = 16; o > 0; o >>= 1) {
        s  += __shfl_down_sync(0xffffffffu, s,  o);
        s2 += __shfl_down_sync(0xffffffffu, s2, o);
    }
    int lane = tid & 31, wid = tid >> 5;
    if (lane == 0) { rs[wid] = s; rs2[wid] = s2; }
    __syncthreads();
    if (tid == 0) {
        float S = 0.f, S2 = 0.f;
        #pragma unroll
        for (int k = 0; k < 8; k++) { S += rs[k]; S2 += rs2[k]; }
        float mean = S * (1.0f / 512.0f);
        float var  = S2 * (1.0f / 512.0f) - mean * mean;
        stat[0] = mean;
        stat[1] = rsqrtf(var + 1e-5f);
    }
    __syncthreads();
    float mean = stat[0], inv = stat[1];
    float* orow = out + (size_t)t * C_DIM;
    orow[tid]       = (v0 - mean) * inv * w[tid]       + b[tid];
    orow[tid + 256] = (v1 - mean) * inv * w[tid + 256] + b[tid + 256];
}

// ---------------- generic tiled SGEMM: C = A(MxK) * B(NxK)^T + bias, with epilogues ----------------
// EPI 0: plain   1: gelu   2: scatter (+res at scattered row, N==512)   3: +res at same row
#define BM 128
#define BN 128
#define BKK 8
template <int EPI>
__global__ void __launch_bounds__(256) k_gemm(const float* __restrict__ A,
                                              const float* __restrict__ Bm,
                                              const float* __restrict__ bias,
                                              float* __restrict__ C,
                                              int M, int N, int K,
                                              const float* __restrict__ res) {
    __shared__ float As[BKK][BM];
    __shared__ float Bs[BKK][BN];
    int tid = threadIdx.x;
    int bm = blockIdx.y * BM, bn = blockIdx.x * BN;
    int tx = tid & 15, ty = tid >> 4;
    float acc[8][8];
    #pragma unroll
    for (int i = 0; i < 8; i++)
        #pragma unroll
        for (int j = 0; j < 8; j++) acc[i][j] = 0.f;

    int lr = tid >> 1;
    int lc = (tid & 1) * 4;
    const float* Ap = A  + (size_t)(bm + lr) * K + lc;
    const float* Bp = Bm + (size_t)(bn + lr) * K + lc;

    for (int k0 = 0; k0 < K; k0 += BKK) {
        float4 av = *(const float4*)(Ap + k0);
        float4 bv = *(const float4*)(Bp + k0);
        As[lc + 0][lr] = av.x; As[lc + 1][lr] = av.y; As[lc + 2][lr] = av.z; As[lc + 3][lr] = av.w;
        Bs[lc + 0][lr] = bv.x; Bs[lc + 1][lr] = bv.y; Bs[lc + 2][lr] = bv.z; Bs[lc + 3][lr] = bv.w;
        __syncthreads();
        #pragma unroll
        for (int kk = 0; kk < BKK; kk++) {
            float a[8], bb[8];
            *(float4*)&a[0]  = *(const float4*)&As[kk][ty * 8];
            *(float4*)&a[4]  = *(const float4*)&As[kk][ty * 8 + 4];
            *(float4*)&bb[0] = *(const float4*)&Bs[kk][tx * 8];
            *(float4*)&bb[4] = *(const float4*)&Bs[kk][tx * 8 + 4];
            #pragma unroll
            for (int i = 0; i < 8; i++)
                #pragma unroll
                for (int j = 0; j < 8; j++) acc[i][j] += a[i] * bb[j];
        }
        __syncthreads();
    }

    #pragma unroll
    for (int i = 0; i < 8; i++) {
        int m = bm + ty * 8 + i;
        size_t orow;
        if (EPI == 2) orow = (size_t)scat_row(m) * C_DIM;
        else          orow = (size_t)m * N;
        #pragma unroll
        for (int j = 0; j < 8; j++) {
            int n = bn + tx * 8 + j;
            float v = acc[i][j] + bias[n];
            if      (EPI == 0) C[orow + n] = v;
            else if (EPI == 1) C[orow + n] = gelu_f(v);
            else               C[orow + n] = res[orow + n] + v;   // EPI 2 & 3
        }
    }
}

// ---------------- reference-token projection ----------------
__global__ void __launch_bounds__(256) k_ref(const float* __restrict__ xr,
                                             const float* __restrict__ W,
                                             const float* __restrict__ bias,
                                             const float* __restrict__ dmu,
                                             const float* __restrict__ dls) {
    __shared__ float xs[C_DIM];
    int rb = blockIdx.x / NREF, r = blockIdx.x % NREF;
    int tid = threadIdx.x;
    const float* src = xr + (size_t)(rb * NREF + r) * C_DIM;
    xs[tid] = src[tid];
    xs[tid + 256] = src[tid + 256];
    __syncthreads();
    int lane = tid & 31, wrp = tid >> 5;
    for (int o = wrp; o < 1024; o += 8) {
        const float* wr = W + (size_t)o * C_DIM;
        float acc = 0.f;
        for (int k = lane; k < C_DIM; k += 32) acc += xs[k] * wr[k];
        #pragma unroll
        for (int s = 16; s > 0; s >>= 1) acc += __shfl_down_sync(0xffffffffu, acc, s);
        if (lane == 0) {
            acc += bias[o];
            int which = o >> 9, c = o & 511;
            int h = c >> 5, d = c & 31;
            size_t dst = ((size_t)(rb * HEADS + h) * NREF + r) * HD + d;
            if (which == 0) g_refq[dst] = dmu[c] + expf(dls[c]) * acc;
            else            g_refv[dst] = acc;
        }
    }
}

// ---------------- ra = q @ ref_q^T, written in conv layout ----------------
__global__ void __launch_bounds__(256) k_ra() {
    int w = blockIdx.x >> 4, h = blockIdx.x & 15;
    int bi = w / NW_PER, wl = w % NW_PER;
    __shared__ float Qs[NWIN * HD];
    __shared__ float Rs[NREF * 33];   // padded stride 33 (bank conflicts)
    int tid = threadIdx.x;
    for (int idx = tid; idx < NWIN * HD; idx += 256) {
        int n = idx >> 5, d = idx & 31;
        Qs[idx] = g_qkv[(size_t)(w * NWIN + n) * 1536 + h * HD + d];
    }
    for (int idx = tid; idx < NREF * HD; idx += 256) {
        int r = idx >> 5, d = idx & 31;
        Rs[r * 33 + d] = g_refq[(size_t)(bi * HEADS + h) * NREF * HD + idx];
    }
    __syncthreads();
    size_t obase = ((size_t)(bi * HEADS + h) * CONV_H + wl * NWIN) * CONV_W;
    for (int o = tid; o < NWIN * NREF; o += 256) {
        int n = o / NREF, r = o % NREF;
        float acc = 0.f;
        #pragma unroll
        for (int k = 0; k < HD; k++) acc += Qs[n * HD + k] * Rs[r * 33 + k];
        g_ra[obase + (size_t)n * CONV_W + r] = acc;
    }
}

// ---------------- 3x3 conv (16->16 channels) over (CONV_H, CONV_W) image ----------------
#define CTH 16
#define CTW 25
__global__ void __launch_bounds__(256) k_conv(const float* __restrict__ cw,
                                              const float* __restrict__ cb) {
    __shared__ float ins[16][CTH + 2][CTW + 2];   // 7776 floats
    __shared__ float ws2[144][16];                // 2304 floats
    int tid = threadIdx.x;
    int b  = blockIdx.z;
    int y0 = blockIdx.y * CTH;
    int x0 = blockIdx.x * CTW;
    for (int idx = tid; idx < 2304; idx += 256) {
        int o = idx / 144, rem = idx % 144;       // cw layout: o*144 + i*9 + kk
        ws2[rem][o] = cw[idx];
    }
    const int TILE = (CTH + 2) * (CTW + 2);
    for (int idx = tid; idx < 16 * TILE; idx += 256) {
        int ci = idx / TILE, rem = idx % TILE;
        int ly = rem / (CTW + 2), lx = rem % (CTW + 2);
        int gy = y0 - 1 + ly, gx = x0 - 1 + lx;
        float v = 0.f;
        if (gy >= 0 && gy < CONV_H && gx >= 0 && gx < CONV_W)
            v = g_ra[((size_t)(b * HEADS + ci) * CONV_H + gy) * CONV_W + gx];
        ins[ci][ly][lx] = v;
    }
    __syncthreads();
    int p0 = tid, p1 = tid + 256;
    int py0 = p0 / CTW, px0 = p0 % CTW;
    int py1 = p1 / CTW, px1 = p1 % CTW;
    bool has1 = (p1 < CTH * CTW);
    float acc0[16], acc1[16];
    #pragma unroll
    for (int o = 0; o < 16; o++) { acc0[o] = cb[o]; acc1[o] = cb[o]; }
    for (int i = 0; i < 16; i++) {
        #pragma unroll
        for (int kk = 0; kk < 9; kk++) {
            int ky = kk / 3, kx = kk % 3;
            float v0 = ins[i][py0 + ky][px0 + kx];
            float v1 = has1 ? ins[i][py1 + ky][px1 + kx] : 0.f;
            const float* wp = ws2[i * 9 + kk];
            #pragma unroll
            for (int o = 0; o < 16; o++) {
                float wv = wp[o];
                acc0[o] += v0 * wv;
                acc1[o] += v1 * wv;
            }
        }
    }
    int gy0 = y0 + py0, gx0 = x0 + px0;
    #pragma unroll
    for (int o = 0; o < 16; o++)
        g_u[((size_t)(b * HEADS + o) * CONV_H + gy0) * CONV_W + gx0] = acc0[o];
    if (has1) {
        int gy1 = y0 + py1, gx1 = x0 + px1;
        #pragma unroll
        for (int o = 0; o < 16; o++)
            g_u[((size_t)(b * HEADS + o) * CONV_H + gy1) * CONV_W + gx1] = acc1[o];
    }
}

__global__ void k_zero_stats() {
    if (threadIdx.x < 64) g_stats[threadIdx.x] = 0.0;
}

__global__ void __launch_bounds__(256) k_red() {
    int bh = blockIdx.y;
    size_t base = (size_t)bh * CONV_HW;
    int tid = threadIdx.x;
    float s = 0.f, s2 = 0.f;
    for (size_t i = (size_t)blockIdx.x * 256 + tid; i < CONV_HW; i += (size_t)gridDim.x * 256) {
        float v = g_u[base + i];
        s += v; s2 += v * v;
    }
    __shared__ float rs[8], rs2[8];
    #pragma unroll
    for (int o = 16; o > 0; o >>= 1) {
        s  += __shfl_down_sync(0xffffffffu, s,  o);
        s2 += __shfl_down_sync(0xffffffffu, s2, o);
    }
    int lane = tid & 31, wid = tid >> 5;
    if (lane == 0) { rs[wid] = s; rs2[wid] = s2; }
    __syncthreads();
    if (tid == 0) {
        double S = 0.0, S2 = 0.0;
        #pragma unroll
        for (int k = 0; k < 8; k++) { S += (double)rs[k]; S2 += (double)rs2[k]; }
        atomicAdd(&g_stats[bh * 2],     S);
        atomicAdd(&g_stats[bh * 2 + 1], S2);
    }
}

__global__ void __launch_bounds__(256) k_fin() {
    size_t idx = (size_t)blockIdx.x * 256 + threadIdx.x;   // grid sized exactly
    int bh = (int)(idx / CONV_HW);
    double cnt = (double)CONV_HW;
    double mu_d  = g_stats[bh * 2] / cnt;
    double var_d = g_stats[bh * 2 + 1] / cnt - mu_d * mu_d;
    float mu  = (float)mu_d;
    float inv = rsqrtf((float)var_d + 1e-5f);
    float t = (g_u[idx] - mu) * inv;
    g_ra[idx] += gelu_f(t);
}

// ---------------- softmax over NREF + q_new = P @ ref_v * SCALE ----------------
__global__ void __launch_bounds__(256) k_softq() {
    int w = blockIdx.x >> 4, h = blockIdx.x & 15;
    int bi = w / NW_PER, wl = w % NW_PER;
    __shared__ float Ps[NWIN * NREF];   // 4900
    __shared__ float Vs[NREF * HD];     // 3200
    int tid = threadIdx.x;
    size_t rbase = ((size_t)(bi * HEADS + h) * CONV_H + wl * NWIN) * CONV_W;
    for (int idx = tid; idx < NWIN * NREF; idx += 256) Ps[idx] = g_ra[rbase + idx];
    for (int idx = tid; idx < NREF * HD; idx += 256)
        Vs[idx] = g_refv[(size_t)(bi * HEADS + h) * NREF * HD + idx];
    __syncthreads();
    int lane = tid & 31, wrp = tid >> 5;
    for (int n = wrp; n < NWIN; n += 8) {
        float* row = Ps + n * NREF;
        float m = -3.4e38f;
        for (int r = lane; r < NREF; r += 32) m = fmaxf(m, row[r]);
        #pragma unroll
        for (int o = 16; o > 0; o >>= 1) m = fmaxf(m, __shfl_xor_sync(0xffffffffu, m, o));
        float s = 0.f;
        for (int r = lane; r < NREF; r += 32) { float e = __expf(row[r] - m); row[r] = e; s += e; }
        #pragma unroll
        for (int o = 16; o > 0; o >>= 1) s += __shfl_xor_sync(0xffffffffu, s, o);
        float inv = 1.f / s;
        for (int r = lane; r < NREF; r += 32) row[r] *= inv;
    }
    __syncthreads();
    for (int o = tid; o < NWIN * HD; o += 256) {
        int n = o >> 5, d = o & 31;
        float acc = 0.f;
        #pragma unroll 4
        for (int r = 0; r < NREF; r++) acc += Ps[n * NREF + r] * Vs[r * HD + d];
        g_qnew[((size_t)(w * HEADS + h) * NWIN + n) * HD + d] = acc * SCALE_ATT;
    }
}

// ---------------- windowed attention: S = q_new k^T + rpb + mask, softmax, @v ----------------
__global__ void __launch_bounds__(256) k_attn(const float* __restrict__ rpb,
                                              const float* __restrict__ mask) {
    int w = blockIdx.x >> 4, h = blockIdx.x & 15;
    int wl = w % NW_PER;
    __shared__ float Qs[NWIN * HD];
    __shared__ float Ks[NWIN * 33];   // padded
    __shared__ float Vs[NWIN * HD];
    __shared__ float Ss[NWIN * 50];
    int tid = threadIdx.x;
    for (int idx = tid; idx < NWIN * HD; idx += 256) {
        int n = idx >> 5, d = idx & 31;
        size_t base = (size_t)(w * NWIN + n) * 1536 + h * HD + d;
        Qs[idx]         = g_qnew[((size_t)(w * HEADS + h) * NWIN + n) * HD + d];
        Ks[n * 33 + d]  = g_qkv[base + 512];
        Vs[idx]         = g_qkv[base + 1024];
    }
    __syncthreads();
    for (int o = tid; o < NWIN * NWIN; o += 256) {
        int n = o / NWIN, m = o % NWIN;
        float acc = 0.f;
        #pragma unroll
        for (int k = 0; k < HD; k++) acc += Qs[n * HD + k] * Ks[m * 33 + k];
        int i1 = n / 7, j1 = n % 7, i2 = m / 7, j2 = m % 7;
        acc += rpb[((i1 - i2 + 6) * 13 + (j1 - j2 + 6)) * HEADS + h];
        acc += mask[((size_t)wl * NWIN + n) * NWIN + m];
        Ss[n * 50 + m] = acc;
    }
    __syncthreads();
    int lane = tid & 31, wrp = tid >> 5;
    for (int n = wrp; n < NWIN; n += 8) {
        float* row = Ss + n * 50;
        float m = -3.4e38f;
        for (int r = lane; r < NWIN; r += 32) m = fmaxf(m, row[r]);
        #pragma unroll
        for (int o = 16; o > 0; o >>= 1) m = fmaxf(m, __shfl_xor_sync(0xffffffffu, m, o));
        float s = 0.f;
        for (int r = lane; r < NWIN; r += 32) { float e = __expf(row[r] - m); row[r] = e; s += e; }
        #pragma unroll
        for (int o = 16; o > 0; o >>= 1) s += __shfl_xor_sync(0xffffffffu, s, o);
        float inv = 1.f / s;
        for (int r = lane; r < NWIN; r += 32) row[r] *= inv;
    }
    __syncthreads();
    for (int o = tid; o < NWIN * HD; o += 256) {
        int n = o >> 5, d = o & 31;
        float acc = 0.f;
        #pragma unroll 7
        for (int m = 0; m < NWIN; m++) acc += Ss[n * 50 + m] * Vs[m * HD + d];
        g_attno[(size_t)(w * NWIN + n) * C_DIM + h * HD + d] = acc;
    }
}

// ---------------- launch ----------------
extern "C" void kernel_launch(void* const* d_in, const int* in_sizes, int n_in,
                              void* d_out, int out_size) {
    (void)in_sizes; (void)n_in; (void)out_size;
    const float* x     = (const float*)d_in[0];
    const float* x_ref = (const float*)d_in[1];
    const float* mask  = (const float*)d_in[2];
    const float* n1w   = (const float*)d_in[3];
    const float* n1b   = (const float*)d_in[4];
    const float* qkvw  = (const float*)d_in[5];
    const float* qkvb  = (const float*)d_in[6];
    const float* dmu   = (const float*)d_in[7];
    const float* dls   = (const float*)d_in[8];
    const float* rpb   = (const float*)d_in[9];
    const float* rqw   = (const float*)d_in[10];
    const float* rqb   = (const float*)d_in[11];
    const float* cw    = (const float*)d_in[12];
    const float* cb    = (const float*)d_in[13];
    const float* pw    = (const float*)d_in[14];
    const float* pb    = (const float*)d_in[15];
    const float* n2w   = (const float*)d_in[16];
    const float* n2b   = (const float*)d_in[17];
    const float* f1w   = (const float*)d_in[18];
    const float* f1b   = (const float*)d_in[19];
    const float* f2w   = (const float*)d_in[20];
    const float* f2b   = (const float*)d_in[21];
    float* out = (float*)d_out;

    float *p_xw, *p_qkv, *p_attno, *p_y, *p_h2, *p_mlp;
    cudaGetSymbolAddress((void**)&p_xw,    g_xw);
    cudaGetSymbolAddress((void**)&p_qkv,   g_qkv);
    cudaGetSymbolAddress((void**)&p_attno, g_attno);
    cudaGetSymbolAddress((void**)&p_y,     g_y);
    cudaGetSymbolAddress((void**)&p_h2,    g_h2);
    cudaGetSymbolAddress((void**)&p_mlp,   g_mlp);

    // 1) LN1 + cyclic shift + window partition
    k_ln<true><<<NTOK, 256>>>(x, n1w, n1b, p_xw);
    // 2) qkv GEMM (25088 x 1536 x 512)
    k_gemm<0><<<dim3(1536 / BN, NTOK / BM), 256>>>(p_xw, qkvw, qkvb, p_qkv,
                                                   NTOK, 1536, C_DIM, nullptr);
    // 3) reference tokens -> ref_q / ref_v
    k_ref<<<B_IMG * NREF, 256>>>(x_ref, rqw, rqb, dmu, dls);
    // 4) ra = q @ ref_q^T (conv layout)
    k_ra<<<B_IMG * NW_PER * HEADS, 256>>>();
    // 5) 3 rounds of conv diffusion + global LN + gelu + residual
    for (int r = 0; r < 3; r++) {
        k_conv<<<dim3(CONV_W / CTW, CONV_H / CTH, B_IMG), 256>>>(cw, cb);
        k_zero_stats<<<1, 64>>>();
        k_red<<<dim3(48, 32), 256>>>();
        k_fin<<<(unsigned)(RA_TOTAL / 256), 256>>>();
    }
    // 6) softmax(ra) @ ref_v * scale
    k_softq<<<B_IMG * NW_PER * HEADS, 256>>>();
    // 7) windowed attention
    k_attn<<<B_IMG * NW_PER * HEADS, 256>>>(rpb, mask);
    // 8) proj GEMM + window-reverse scatter + residual with x  -> y
    k_gemm<2><<<dim3(C_DIM / BN, NTOK / BM), 256>>>(p_attno, pw, pb, p_y,
                                                    NTOK, C_DIM, C_DIM, x);
    // 9) LN2
    k_ln<false><<<NTOK, 256>>>(p_y, n2w, n2b, p_h2);
    // 10) fc1 + gelu
    k_gemm<1><<<dim3(2048 / BN, NTOK / BM), 256>>>(p_h2, f1w, f1b, p_mlp,
                                                   NTOK, 2048, C_DIM, nullptr);
    // 11) fc2 + residual with y -> out
    k_gemm<3><<<dim3(C_DIM / BN, NTOK / BM), 256>>>(p_mlp, f2w, f2b, out,
                                                    NTOK, C_DIM, 2048, p_y);
}

// round 9
// speedup vs baseline: 1.0132x; 1.0132x over previous
#include <cuda_runtime.h>
#include <cuda_bf16.h>
#include <math.h>

// ---------------- problem constants ----------------
#define WSZ 7
#define SHIFT_SZ 3
#define HEADS 16
#define C_DIM 512
#define HD 32
#define NREF 100
#define H_IMG 112
#define NWX 16            // windows per row = 112/7
#define NW_PER 256        // windows per image
#define B_IMG 2
#define NWIN 49           // tokens per window
#define L_IMG 12544       // 112*112
#define NTOK 25088        // B_IMG * L_IMG
#define CONV_H 12544      // NW_PER * NWIN
#define CONV_W 100        // NREF
#define CONV_HW 1254400
#define RA_TOTAL 40140800ll   // 2*16*CONV_HW
#define SCALE_ATT 0.17677669529663687f

typedef unsigned long long ull;

// ---------------- scratch (static device globals; no allocation) ----------------
__device__ float g_xw   [(size_t)NTOK * C_DIM];        // LN1 + shifted-window partition
__device__ float g_qkv  [(size_t)NTOK * 3 * C_DIM];    // fused qkv, layout (tok, 3*512)
__device__ float g_refq [B_IMG * HEADS * NREF * HD];
__device__ float g_refv [B_IMG * HEADS * NREF * HD];
__device__ float g_ra   [(size_t)B_IMG * HEADS * CONV_HW];  // conv-layout ra
__device__ float g_u    [(size_t)B_IMG * HEADS * CONV_HW];  // conv output scratch
__device__ double g_stats[64];                              // per-(b,h) sum / sumsq
__device__ float g_qnew [(size_t)NTOK * C_DIM];        // (w,h,n,d)
__device__ float g_attno[(size_t)NTOK * C_DIM];        // attention out (tok, C)
__device__ float g_y    [(size_t)NTOK * C_DIM];        // x + attn (B,L,C)
__device__ float g_h2   [(size_t)NTOK * C_DIM];        // LN2 out
__device__ float g_mlp  [(size_t)NTOK * 4 * C_DIM];    // fc1+gelu out

// ---------------- helpers ----------------
__device__ __forceinline__ float gelu_f(float x) {
    return 0.5f * x * (1.0f + erff(x * 0.70710678118654752f));
}

__device__ __forceinline__ ull dup_f32x2(float v) {
    ull r;
    asm("mov.b64 %0, {%1, %1};" : "=l"(r) : "r"(__float_as_uint(v)));
    return r;
}
__device__ __forceinline__ ull pack_f32x2(float lo, float hi) {
    ull r;
    asm("mov.b64 %0, {%1, %2};" : "=l"(r) : "r"(__float_as_uint(lo)), "r"(__float_as_uint(hi)));
    return r;
}
__device__ __forceinline__ void unpack_f32x2(ull v, float& lo, float& hi) {
    unsigned ulo, uhi;
    asm("mov.b64 {%0, %1}, %2;" : "=r"(ulo), "=r"(uhi) : "l"(v));
    lo = __uint_as_float(ulo);
    hi = __uint_as_float(uhi);
}
__device__ __forceinline__ void fma_f32x2(ull& acc, ull a, ull b) {
    asm("fma.rn.f32x2 %0, %1, %2, %0;" : "+l"(acc) : "l"(a), "l"(b));
}

// token index -> (b, l) row in the original (B, L) layout (shifted-window map)
__device__ __forceinline__ int scat_row(int t) {
    int w  = t / NWIN, n = t % NWIN;
    int bi = w / NW_PER, wl = w % NW_PER;
    int wr = wl / NWX,  wc = wl % NWX;
    int i  = n / WSZ,   j  = n % WSZ;
    int hh = (wr * WSZ + i + SHIFT_SZ) % H_IMG;
    int ww = (wc * WSZ + j + SHIFT_SZ) % H_IMG;
    return bi * L_IMG + hh * H_IMG + ww;
}

// ---------------- LayerNorm (optionally gathering through shifted-window map) ----------------
template <bool GATHER>
__global__ void __launch_bounds__(256) k_ln(const float* __restrict__ in,
                                            const float* __restrict__ w,
                                            const float* __restrict__ b,
                                            float* __restrict__ out) {
    int t   = blockIdx.x;
    int src = GATHER ? scat_row(t) : t;
    const float* row = in + (size_t)src * C_DIM;
    int tid = threadIdx.x;
    float v0 = row[tid], v1 = row[tid + 256];
    float s = v0 + v1, s2 = v0 * v0 + v1 * v1;
    __shared__ float rs[8], rs2[8], stat[2];
    #pragma unroll
    for (int o = 16; o > 0; o >>= 1) {
        s  += __shfl_down_sync(0xffffffffu, s,  o);
        s2 += __shfl_down_sync(0xffffffffu, s2, o);
    }
    int lane = tid & 31, wid = tid >> 5;
    if (lane == 0) { rs[wid] = s; rs2[wid] = s2; }
    __syncthreads();
    if (tid == 0) {
        float S = 0.f, S2 = 0.f;
        #pragma unroll
        for (int k = 0; k < 8; k++) { S += rs[k]; S2 += rs2[k]; }
        float mean = S * (1.0f / 512.0f);
        float var  = S2 * (1.0f / 512.0f) - mean * mean;
        stat[0] = mean;
        stat[1] = rsqrtf(var + 1e-5f);
    }
    __syncthreads();
    float mean = stat[0], inv = stat[1];
    float* orow = out + (size_t)t * C_DIM;
    orow[tid]       = (v0 - mean) * inv * w[tid]       + b[tid];
    orow[tid + 256] = (v1 - mean) * inv * w[tid + 256] + b[tid + 256];
}

// ---------------- generic tiled SGEMM: C = A(MxK) * B(NxK)^T + bias, with epilogues ----------------
// EPI 0: plain   1: gelu   2: scatter (+res at scattered row, N==512)   3: +res at same row
// Inner loop uses packed f32x2 FMA (FFMA2): 2x fp32 throughput, bit-exact fp32 math.
#define BM 128
#define BN 128
#define BKK 8
template <int EPI>
__global__ void __launch_bounds__(256) k_gemm(const float* __restrict__ A,
                                              const float* __restrict__ Bm,
                                              const float* __restrict__ bias,
                                              float* __restrict__ C,
                                              int M, int N, int K,
                                              const float* __restrict__ res) {
    __shared__ __align__(16) float As[BKK][BM];
    __shared__ __align__(16) float Bs[BKK][BN];
    int tid = threadIdx.x;
    int bm = blockIdx.y * BM, bn = blockIdx.x * BN;
    int tx = tid & 15, ty = tid >> 4;
    ull acc2[8][4];   // 8 rows x 4 f32x2 pairs (covers 8 N-columns)
    #pragma unroll
    for (int i = 0; i < 8; i++)
        #pragma unroll
        for (int j = 0; j < 4; j++) acc2[i][j] = 0ull;   // bit pattern of (+0.f, +0.f)

    int lr = tid >> 1;
    int lc = (tid & 1) * 4;
    const float* Ap = A  + (size_t)(bm + lr) * K + lc;
    const float* Bp = Bm + (size_t)(bn + lr) * K + lc;

    for (int k0 = 0; k0 < K; k0 += BKK) {
        float4 av = *(const float4*)(Ap + k0);
        float4 bv = *(const float4*)(Bp + k0);
        As[lc + 0][lr] = av.x; As[lc + 1][lr] = av.y; As[lc + 2][lr] = av.z; As[lc + 3][lr] = av.w;
        Bs[lc + 0][lr] = bv.x; Bs[lc + 1][lr] = bv.y; Bs[lc + 2][lr] = bv.z; Bs[lc + 3][lr] = bv.w;
        __syncthreads();
        #pragma unroll
        for (int kk = 0; kk < BKK; kk++) {
            float a[8];
            ull b2[4];
            *(float4*)&a[0]  = *(const float4*)&As[kk][ty * 8];
            *(float4*)&a[4]  = *(const float4*)&As[kk][ty * 8 + 4];
            const ull* bp = (const ull*)&Bs[kk][tx * 8];   // 32B-aligned
            b2[0] = bp[0]; b2[1] = bp[1]; b2[2] = bp[2]; b2[3] = bp[3];
            #pragma unroll
            for (int i = 0; i < 8; i++) {
                ull a2 = dup_f32x2(a[i]);
                #pragma unroll
                for (int j = 0; j < 4; j++) fma_f32x2(acc2[i][j], a2, b2[j]);
            }
        }
        __syncthreads();
    }

    #pragma unroll
    for (int i = 0; i < 8; i++) {
        int m = bm + ty * 8 + i;
        size_t orow;
        if (EPI == 2) orow = (size_t)scat_row(m) * C_DIM;
        else          orow = (size_t)m * N;
        #pragma unroll
        for (int j = 0; j < 4; j++) {
            int n0 = bn + tx * 8 + j * 2;
            float c0, c1;
            unpack_f32x2(acc2[i][j], c0, c1);
            float v0 = c0 + bias[n0];
            float v1 = c1 + bias[n0 + 1];
            if (EPI == 0) {
                C[orow + n0] = v0;         C[orow + n0 + 1] = v1;
            } else if (EPI == 1) {
                C[orow + n0] = gelu_f(v0); C[orow + n0 + 1] = gelu_f(v1);
            } else {
                C[orow + n0]     = res[orow + n0]     + v0;
                C[orow + n0 + 1] = res[orow + n0 + 1] + v1;
            }
        }
    }
}

// ---------------- reference-token projection ----------------
__global__ void __launch_bounds__(256) k_ref(const float* __restrict__ xr,
                                             const float* __restrict__ W,
                                             const float* __restrict__ bias,
                                             const float* __restrict__ dmu,
                                             const float* __restrict__ dls) {
    __shared__ float xs[C_DIM];
    int rb = blockIdx.x / NREF, r = blockIdx.x % NREF;
    int tid = threadIdx.x;
    const float* src = xr + (size_t)(rb * NREF + r) * C_DIM;
    xs[tid] = src[tid];
    xs[tid + 256] = src[tid + 256];
    __syncthreads();
    int lane = tid & 31, wrp = tid >> 5;
    for (int o = wrp; o < 1024; o += 8) {
        const float* wr = W + (size_t)o * C_DIM;
        float acc = 0.f;
        for (int k = lane; k < C_DIM; k += 32) acc += xs[k] * wr[k];
        #pragma unroll
        for (int s = 16; s > 0; s >>= 1) acc += __shfl_down_sync(0xffffffffu, acc, s);
        if (lane == 0) {
            acc += bias[o];
            int which = o >> 9, c = o & 511;
            int h = c >> 5, d = c & 31;
            size_t dst = ((size_t)(rb * HEADS + h) * NREF + r) * HD + d;
            if (which == 0) g_refq[dst] = dmu[c] + expf(dls[c]) * acc;
            else            g_refv[dst] = acc;
        }
    }
}

// ---------------- ra = q @ ref_q^T, written in conv layout ----------------
__global__ void __launch_bounds__(256) k_ra() {
    int w = blockIdx.x >> 4, h = blockIdx.x & 15;
    int bi = w / NW_PER, wl = w % NW_PER;
    __shared__ __align__(16) float Qs[NWIN * HD];
    __shared__ __align__(16) float Rs[NREF * 34];   // even stride (8B-aligned pairs)
    int tid = threadIdx.x;
    for (int idx = tid; idx < NWIN * HD; idx += 256) {
        int n = idx >> 5, d = idx & 31;
        Qs[idx] = g_qkv[(size_t)(w * NWIN + n) * 1536 + h * HD + d];
    }
    for (int idx = tid; idx < NREF * HD; idx += 256) {
        int r = idx >> 5, d = idx & 31;
        Rs[r * 34 + d] = g_refq[(size_t)(bi * HEADS + h) * NREF * HD + idx];
    }
    __syncthreads();
    size_t obase = ((size_t)(bi * HEADS + h) * CONV_H + wl * NWIN) * CONV_W;
    for (int o = tid; o < NWIN * NREF; o += 256) {
        int n = o / NREF, r = o % NREF;
        const ull* qp = (const ull*)&Qs[n * HD];
        const ull* rp = (const ull*)&Rs[r * 34];
        ull a2 = 0ull;
        #pragma unroll
        for (int k2 = 0; k2 < HD / 2; k2++) fma_f32x2(a2, qp[k2], rp[k2]);
        float lo, hi;
        unpack_f32x2(a2, lo, hi);
        g_ra[obase + (size_t)n * CONV_W + r] = lo + hi;
    }
}

// ---------------- 3x3 conv (16->16 channels) over (CONV_H, CONV_W) image ----------------
#define CTH 16
#define CTW 25
__global__ void __launch_bounds__(256) k_conv(const float* __restrict__ cw,
                                              const float* __restrict__ cb) {
    __shared__ float ins[16][CTH + 2][CTW + 2];            // 7776 floats
    __shared__ __align__(16) float ws2[144][16];           // 2304 floats
    int tid = threadIdx.x;
    int b  = blockIdx.z;
    int y0 = blockIdx.y * CTH;
    int x0 = blockIdx.x * CTW;
    for (int idx = tid; idx < 2304; idx += 256) {
        int o = idx / 144, rem = idx % 144;       // cw layout: o*144 + i*9 + kk
        ws2[rem][o] = cw[idx];
    }
    const int TILE = (CTH + 2) * (CTW + 2);
    for (int idx = tid; idx < 16 * TILE; idx += 256) {
        int ci = idx / TILE, rem = idx % TILE;
        int ly = rem / (CTW + 2), lx = rem % (CTW + 2);
        int gy = y0 - 1 + ly, gx = x0 - 1 + lx;
        float v = 0.f;
        if (gy >= 0 && gy < CONV_H && gx >= 0 && gx < CONV_W)
            v = g_ra[((size_t)(b * HEADS + ci) * CONV_H + gy) * CONV_W + gx];
        ins[ci][ly][lx] = v;
    }
    __syncthreads();
    int p0 = tid, p1 = tid + 256;
    int py0 = p0 / CTW, px0 = p0 % CTW;
    int py1 = p1 / CTW, px1 = p1 % CTW;
    bool has1 = (p1 < CTH * CTW);
    ull acc0[8], acc1[8];
    #pragma unroll
    for (int o2 = 0; o2 < 8; o2++) {
        ull init = pack_f32x2(cb[o2 * 2], cb[o2 * 2 + 1]);
        acc0[o2] = init; acc1[o2] = init;
    }
    for (int i = 0; i < 16; i++) {
        #pragma unroll
        for (int kk = 0; kk < 9; kk++) {
            int ky = kk / 3, kx = kk % 3;
            ull v0d = dup_f32x2(ins[i][py0 + ky][px0 + kx]);
            ull v1d = dup_f32x2(has1 ? ins[i][py1 + ky][px1 + kx] : 0.f);
            const ull* wp = (const ull*)ws2[i * 9 + kk];   // row is 64B-aligned
            #pragma unroll
            for (int o2 = 0; o2 < 8; o2++) {
                ull wv = wp[o2];
                fma_f32x2(acc0[o2], v0d, wv);
                fma_f32x2(acc1[o2], v1d, wv);
            }
        }
    }
    int gy0 = y0 + py0, gx0 = x0 + px0;
    #pragma unroll
    for (int o2 = 0; o2 < 8; o2++) {
        float lo, hi;
        unpack_f32x2(acc0[o2], lo, hi);
        g_u[((size_t)(b * HEADS + o2 * 2)     * CONV_H + gy0) * CONV_W + gx0] = lo;
        g_u[((size_t)(b * HEADS + o2 * 2 + 1) * CONV_H + gy0) * CONV_W + gx0] = hi;
    }
    if (has1) {
        int gy1 = y0 + py1, gx1 = x0 + px1;
        #pragma unroll
        for (int o2 = 0; o2 < 8; o2++) {
            float lo, hi;
            unpack_f32x2(acc1[o2], lo, hi);
            g_u[((size_t)(b * HEADS + o2 * 2)     * CONV_H + gy1) * CONV_W + gx1] = lo;
            g_u[((size_t)(b * HEADS + o2 * 2 + 1) * CONV_H + gy1) * CONV_W + gx1] = hi;
        }
    }
}

__global__ void k_zero_stats() {
    if (threadIdx.x < 64) g_stats[threadIdx.x] = 0.0;
}

__global__ void __launch_bounds__(256) k_red() {
    int bh = blockIdx.y;
    size_t base = (size_t)bh * CONV_HW;
    int tid = threadIdx.x;
    float s = 0.f, s2 = 0.f;
    for (size_t i = (size_t)blockIdx.x * 256 + tid; i < CONV_HW; i += (size_t)gridDim.x * 256) {
        float v = g_u[base + i];
        s += v; s2 += v * v;
    }
    __shared__ float rs[8], rs2[8];
    #pragma unroll
    for (int o = 16; o > 0; o >>= 1) {
        s  += __shfl_down_sync(0xffffffffu, s,  o);
        s2 += __shfl_down_sync(0xffffffffu, s2, o);
    }
    int lane = tid & 31, wid = tid >> 5;
    if (lane == 0) { rs[wid] = s; rs2[wid] = s2; }
    __syncthreads();
    if (tid == 0) {
        double S = 0.0, S2 = 0.0;
        #pragma unroll
        for (int k = 0; k < 8; k++) { S += (double)rs[k]; S2 += (double)rs2[k]; }
        atomicAdd(&g_stats[bh * 2],     S);
        atomicAdd(&g_stats[bh * 2 + 1], S2);
    }
}

__global__ void __launch_bounds__(256) k_fin() {
    size_t idx = (size_t)blockIdx.x * 256 + threadIdx.x;   // grid sized exactly
    int bh = (int)(idx / CONV_HW);
    double cnt = (double)CONV_HW;
    double mu_d  = g_stats[bh * 2] / cnt;
    double var_d = g_stats[bh * 2 + 1] / cnt - mu_d * mu_d;
    float mu  = (float)mu_d;
    float inv = rsqrtf((float)var_d + 1e-5f);
    float t = (g_u[idx] - mu) * inv;
    g_ra[idx] += gelu_f(t);
}

// ---------------- softmax over NREF + q_new = P @ ref_v * SCALE ----------------
__global__ void __launch_bounds__(256) k_softq() {
    int w = blockIdx.x >> 4, h = blockIdx.x & 15;
    int bi = w / NW_PER, wl = w % NW_PER;
    __shared__ float Ps[NWIN * NREF];   // 4900
    __shared__ float Vs[NREF * HD];     // 3200
    int tid = threadIdx.x;
    size_t rbase = ((size_t)(bi * HEADS + h) * CONV_H + wl * NWIN) * CONV_W;
    for (int idx = tid; idx < NWIN * NREF; idx += 256) Ps[idx] = g_ra[rbase + idx];
    for (int idx = tid; idx < NREF * HD; idx += 256)
        Vs[idx] = g_refv[(size_t)(bi * HEADS + h) * NREF * HD + idx];
    __syncthreads();
    int lane = tid & 31, wrp = tid >> 5;
    for (int n = wrp; n < NWIN; n += 8) {
        float* row = Ps + n * NREF;
        float m = -3.4e38f;
        for (int r = lane; r < NREF; r += 32) m = fmaxf(m, row[r]);
        #pragma unroll
        for (int o = 16; o > 0; o >>= 1) m = fmaxf(m, __shfl_xor_sync(0xffffffffu, m, o));
        float s = 0.f;
        for (int r = lane; r < NREF; r += 32) { float e = __expf(row[r] - m); row[r] = e; s += e; }
        #pragma unroll
        for (int o = 16; o > 0; o >>= 1) s += __shfl_xor_sync(0xffffffffu, s, o);
        float inv = 1.f / s;
        for (int r = lane; r < NREF; r += 32) row[r] *= inv;
    }
    __syncthreads();
    for (int o = tid; o < NWIN * HD; o += 256) {
        int n = o >> 5, d = o & 31;
        float acc = 0.f;
        #pragma unroll 4
        for (int r = 0; r < NREF; r++) acc += Ps[n * NREF + r] * Vs[r * HD + d];
        g_qnew[((size_t)(w * HEADS + h) * NWIN + n) * HD + d] = acc * SCALE_ATT;
    }
}

// ---------------- windowed attention: S = q_new k^T + rpb + mask, softmax, @v ----------------
__global__ void __launch_bounds__(256) k_attn(const float* __restrict__ rpb,
                                              const float* __restrict__ mask) {
    int w = blockIdx.x >> 4, h = blockIdx.x & 15;
    int wl = w % NW_PER;
    __shared__ float Qs[NWIN * HD];
    __shared__ float Ks[NWIN * 33];   // padded
    __shared__ float Vs[NWIN * HD];
    __shared__ float Ss[NWIN * 50];
    int tid = threadIdx.x;
    for (int idx = tid; idx < NWIN * HD; idx += 256) {
        int n = idx >> 5, d = idx & 31;
        size_t base = (size_t)(w * NWIN + n) * 1536 + h * HD + d;
        Qs[idx]         = g_qnew[((size_t)(w * HEADS + h) * NWIN + n) * HD + d];
        Ks[n * 33 + d]  = g_qkv[base + 512];
        Vs[idx]         = g_qkv[base + 1024];
    }
    __syncthreads();
    for (int o = tid; o < NWIN * NWIN; o += 256) {
        int n = o / NWIN, m = o % NWIN;
        float acc = 0.f;
        #pragma unroll
        for (int k = 0; k < HD; k++) acc += Qs[n * HD + k] * Ks[m * 33 + k];
        int i1 = n / 7, j1 = n % 7, i2 = m / 7, j2 = m % 7;
        acc += rpb[((i1 - i2 + 6) * 13 + (j1 - j2 + 6)) * HEADS + h];
        acc += mask[((size_t)wl * NWIN + n) * NWIN + m];
        Ss[n * 50 + m] = acc;
    }
    __syncthreads();
    int lane = tid & 31, wrp = tid >> 5;
    for (int n = wrp; n < NWIN; n += 8) {
        float* row = Ss + n * 50;
        float m = -3.4e38f;
        for (int r = lane; r < NWIN; r += 32) m = fmaxf(m, row[r]);
        #pragma unroll
        for (int o = 16; o > 0; o >>= 1) m = fmaxf(m, __shfl_xor_sync(0xffffffffu, m, o));
        float s = 0.f;
        for (int r = lane; r < NWIN; r += 32) { float e = __expf(row[r] - m); row[r] = e; s += e; }
        #pragma unroll
        for (int o = 16; o > 0; o >>= 1) s += __shfl_xor_sync(0xffffffffu, s, o);
        float inv = 1.f / s;
        for (int r = lane; r < NWIN; r += 32) row[r] *= inv;
    }
    __syncthreads();
    for (int o = tid; o < NWIN * HD; o += 256) {
        int n = o >> 5, d = o & 31;
        float acc = 0.f;
        #pragma unroll 7
        for (int m = 0; m < NWIN; m++) acc += Ss[n * 50 + m] * Vs[m * HD + d];
        g_attno[(size_t)(w * NWIN + n) * C_DIM + h * HD + d] = acc;
    }
}

// ---------------- launch ----------------
extern "C" void kernel_launch(void* const* d_in, const int* in_sizes, int n_in,
                              void* d_out, int out_size) {
    (void)in_sizes; (void)n_in; (void)out_size;
    const float* x     = (const float*)d_in[0];
    const float* x_ref = (const float*)d_in[1];
    const float* mask  = (const float*)d_in[2];
    const float* n1w   = (const float*)d_in[3];
    const float* n1b   = (const float*)d_in[4];
    const float* qkvw  = (const float*)d_in[5];
    const float* qkvb  = (const float*)d_in[6];
    const float* dmu   = (const float*)d_in[7];
    const float* dls   = (const float*)d_in[8];
    const float* rpb   = (const float*)d_in[9];
    const float* rqw   = (const float*)d_in[10];
    const float* rqb   = (const float*)d_in[11];
    const float* cw    = (const float*)d_in[12];
    const float* cb    = (const float*)d_in[13];
    const float* pw    = (const float*)d_in[14];
    const float* pb    = (const float*)d_in[15];
    const float* n2w   = (const float*)d_in[16];
    const float* n2b   = (const float*)d_in[17];
    const float* f1w   = (const float*)d_in[18];
    const float* f1b   = (const float*)d_in[19];
    const float* f2w   = (const float*)d_in[20];
    const float* f2b   = (const float*)d_in[21];
    float* out = (float*)d_out;

    float *p_xw, *p_qkv, *p_attno, *p_y, *p_h2, *p_mlp;
    cudaGetSymbolAddress((void**)&p_xw,    g_xw);
    cudaGetSymbolAddress((void**)&p_qkv,   g_qkv);
    cudaGetSymbolAddress((void**)&p_attno, g_attno);
    cudaGetSymbolAddress((void**)&p_y,     g_y);
    cudaGetSymbolAddress((void**)&p_h2,    g_h2);
    cudaGetSymbolAddress((void**)&p_mlp,   g_mlp);

    // 1) LN1 + cyclic shift + window partition
    k_ln<true><<<NTOK, 256>>>(x, n1w, n1b, p_xw);
    // 2) qkv GEMM (25088 x 1536 x 512)
    k_gemm<0><<<dim3(1536 / BN, NTOK / BM), 256>>>(p_xw, qkvw, qkvb, p_qkv,
                                                   NTOK, 1536, C_DIM, nullptr);
    // 3) reference tokens -> ref_q / ref_v
    k_ref<<<B_IMG * NREF, 256>>>(x_ref, rqw, rqb, dmu, dls);
    // 4) ra = q @ ref_q^T (conv layout)
    k_ra<<<B_IMG * NW_PER * HEADS, 256>>>();
    // 5) 3 rounds of conv diffusion + global LN + gelu + residual
    for (int r = 0; r < 3; r++) {
        k_conv<<<dim3(CONV_W / CTW, CONV_H / CTH, B_IMG), 256>>>(cw, cb);
        k_zero_stats<<<1, 64>>>();
        k_red<<<dim3(48, 32), 256>>>();
        k_fin<<<(unsigned)(RA_TOTAL / 256), 256>>>();
    }
    // 6) softmax(ra) @ ref_v * scale
    k_softq<<<B_IMG * NW_PER * HEADS, 256>>>();
    // 7) windowed attention
    k_attn<<<B_IMG * NW_PER * HEADS, 256>>>(rpb, mask);
    // 8) proj GEMM + window-reverse scatter + residual with x  -> y
    k_gemm<2><<<dim3(C_DIM / BN, NTOK / BM), 256>>>(p_attno, pw, pb, p_y,
                                                    NTOK, C_DIM, C_DIM, x);
    // 9) LN2
    k_ln<false><<<NTOK, 256>>>(p_y, n2w, n2b, p_h2);
    // 10) fc1 + gelu
    k_gemm<1><<<dim3(2048 / BN, NTOK / BM), 256>>>(p_h2, f1w, f1b, p_mlp,
                                                   NTOK, 2048, C_DIM, nullptr);
    // 11) fc2 + residual with y -> out
    k_gemm<3><<<dim3(C_DIM / BN, NTOK / BM), 256>>>(p_mlp, f2w, f2b, out,
                                                    NTOK, C_DIM, 2048, p_y);
}

// round 12
// speedup vs baseline: 1.6081x; 1.5871x over previous
#include <cuda_runtime.h>
#include <cuda_bf16.h>
#include <math.h>

// ---------------- problem constants ----------------
#define WSZ 7
#define SHIFT_SZ 3
#define HEADS 16
#define C_DIM 512
#define HD 32
#define NREF 100
#define H_IMG 112
#define NWX 16            // windows per row = 112/7
#define NW_PER 256        // windows per image
#define B_IMG 2
#define NWIN 49           // tokens per window
#define L_IMG 12544       // 112*112
#define NTOK 25088        // B_IMG * L_IMG
#define CONV_H 12544      // NW_PER * NWIN
#define CONV_W 100        // NREF
#define CONV_HW 1254400
#define RA_TOTAL 40140800ll   // 2*16*CONV_HW
#define SCALE_ATT 0.17677669529663687f

typedef unsigned long long ull;

// ---------------- scratch (static device globals; no allocation) ----------------
__device__ float g_xw   [(size_t)NTOK * C_DIM];        // LN1 + shifted-window partition
__device__ float g_qkv  [(size_t)NTOK * 3 * C_DIM];    // fused qkv, layout (tok, 3*512)
__device__ float g_refq [B_IMG * HEADS * NREF * HD];
__device__ float g_refv [B_IMG * HEADS * NREF * HD];
__device__ float g_ra   [(size_t)B_IMG * HEADS * CONV_HW];  // conv-layout ra
__device__ float g_u    [(size_t)B_IMG * HEADS * CONV_HW];  // conv output scratch
__device__ double g_stats[64];                              // per-(b,h) sum / sumsq
__device__ float g_mu [32];                                 // finalized per-(b,h) mean
__device__ float g_inv[32];                                 // finalized per-(b,h) rsqrt(var+eps)
__device__ float g_qnew [(size_t)NTOK * C_DIM];        // (w,h,n,d)
__device__ float g_attno[(size_t)NTOK * C_DIM];        // attention out (tok, C)
__device__ float g_y    [(size_t)NTOK * C_DIM];        // x + attn (B,L,C)
__device__ float g_h2   [(size_t)NTOK * C_DIM];        // LN2 out
__device__ float g_mlp  [(size_t)NTOK * 4 * C_DIM];    // fc1+gelu out

// ---------------- helpers ----------------
__device__ __forceinline__ float gelu_f(float x) {
    return 0.5f * x * (1.0f + erff(x * 0.70710678118654752f));
}

__device__ __forceinline__ ull dup_f32x2(float v) {
    ull r;
    asm("mov.b64 %0, {%1, %1};" : "=l"(r) : "r"(__float_as_uint(v)));
    return r;
}
__device__ __forceinline__ ull pack_f32x2(float lo, float hi) {
    ull r;
    asm("mov.b64 %0, {%1, %2};" : "=l"(r) : "r"(__float_as_uint(lo)), "r"(__float_as_uint(hi)));
    return r;
}
__device__ __forceinline__ void unpack_f32x2(ull v, float& lo, float& hi) {
    unsigned ulo, uhi;
    asm("mov.b64 {%0, %1}, %2;" : "=r"(ulo), "=r"(uhi) : "l"(v));
    lo = __uint_as_float(ulo);
    hi = __uint_as_float(uhi);
}
__device__ __forceinline__ void fma_f32x2(ull& acc, ull a, ull b) {
    asm("fma.rn.f32x2 %0, %1, %2, %0;" : "+l"(acc) : "l"(a), "l"(b));
}

// token index -> (b, l) row in the original (B, L) layout (shifted-window map)
__device__ __forceinline__ int scat_row(int t) {
    int w  = t / NWIN, n = t % NWIN;
    int bi = w / NW_PER, wl = w % NW_PER;
    int wr = wl / NWX,  wc = wl % NWX;
    int i  = n / WSZ,   j  = n % WSZ;
    int hh = (wr * WSZ + i + SHIFT_SZ) % H_IMG;
    int ww = (wc * WSZ + j + SHIFT_SZ) % H_IMG;
    return bi * L_IMG + hh * H_IMG + ww;
}

// ---------------- LayerNorm (optionally gathering through shifted-window map) ----------------
template <bool GATHER>
__global__ void __launch_bounds__(256) k_ln(const float* __restrict__ in,
                                            const float* __restrict__ w,
                                            const float* __restrict__ b,
                                            float* __restrict__ out) {
    int t   = blockIdx.x;
    int src = GATHER ? scat_row(t) : t;
    const float* row = in + (size_t)src * C_DIM;
    int tid = threadIdx.x;
    float v0 = row[tid], v1 = row[tid + 256];
    float s = v0 + v1, s2 = v0 * v0 + v1 * v1;
    __shared__ float rs[8], rs2[8], stat[2];
    #pragma unroll
    for (int o = 16; o > 0; o >>= 1) {
        s  += __shfl_down_sync(0xffffffffu, s,  o);
        s2 += __shfl_down_sync(0xffffffffu, s2, o);
    }
    int lane = tid & 31, wid = tid >> 5;
    if (lane == 0) { rs[wid] = s; rs2[wid] = s2; }
    __syncthreads();
    if (tid == 0) {
        float S = 0.f, S2 = 0.f;
        #pragma unroll
        for (int k = 0; k < 8; k++) { S += rs[k]; S2 += rs2[k]; }
        float mean = S * (1.0f / 512.0f);
        float var  = S2 * (1.0f / 512.0f) - mean * mean;
        stat[0] = mean;
        stat[1] = rsqrtf(var + 1e-5f);
    }
    __syncthreads();
    float mean = stat[0], inv = stat[1];
    float* orow = out + (size_t)t * C_DIM;
    orow[tid]       = (v0 - mean) * inv * w[tid]       + b[tid];
    orow[tid + 256] = (v1 - mean) * inv * w[tid + 256] + b[tid + 256];
}

// ---------------- generic tiled SGEMM: C = A(MxK) * B(NxK)^T + bias, with epilogues ----------------
// EPI 0: plain   1: gelu   2: scatter (+res at scattered row, N==512)   3: +res at same row
// Inner loop uses packed f32x2 FMA (FFMA2): 2x fp32 throughput, bit-exact fp32 math.
#define BM 128
#define BN 128
#define BKK 8
template <int EPI>
__global__ void __launch_bounds__(256) k_gemm(const float* __restrict__ A,
                                              const float* __restrict__ Bm,
                                              const float* __restrict__ bias,
                                              float* __restrict__ C,
                                              int M, int N, int K,
                                              const float* __restrict__ res) {
    __shared__ __align__(16) float As[BKK][BM];
    __shared__ __align__(16) float Bs[BKK][BN];
    int tid = threadIdx.x;
    int bm = blockIdx.y * BM, bn = blockIdx.x * BN;
    int tx = tid & 15, ty = tid >> 4;
    ull acc2[8][4];   // 8 rows x 4 f32x2 pairs (covers 8 N-columns)
    #pragma unroll
    for (int i = 0; i < 8; i++)
        #pragma unroll
        for (int j = 0; j < 4; j++) acc2[i][j] = 0ull;   // bit pattern of (+0.f, +0.f)

    int lr = tid >> 1;
    int lc = (tid & 1) * 4;
    const float* Ap = A  + (size_t)(bm + lr) * K + lc;
    const float* Bp = Bm + (size_t)(bn + lr) * K + lc;

    for (int k0 = 0; k0 < K; k0 += BKK) {
        float4 av = *(const float4*)(Ap + k0);
        float4 bv = *(const float4*)(Bp + k0);
        As[lc + 0][lr] = av.x; As[lc + 1][lr] = av.y; As[lc + 2][lr] = av.z; As[lc + 3][lr] = av.w;
        Bs[lc + 0][lr] = bv.x; Bs[lc + 1][lr] = bv.y; Bs[lc + 2][lr] = bv.z; Bs[lc + 3][lr] = bv.w;
        __syncthreads();
        #pragma unroll
        for (int kk = 0; kk < BKK; kk++) {
            float a[8];
            ull b2[4];
            *(float4*)&a[0]  = *(const float4*)&As[kk][ty * 8];
            *(float4*)&a[4]  = *(const float4*)&As[kk][ty * 8 + 4];
            const ull* bp = (const ull*)&Bs[kk][tx * 8];   // 32B-aligned
            b2[0] = bp[0]; b2[1] = bp[1]; b2[2] = bp[2]; b2[3] = bp[3];
            #pragma unroll
            for (int i = 0; i < 8; i++) {
                ull a2 = dup_f32x2(a[i]);
                #pragma unroll
                for (int j = 0; j < 4; j++) fma_f32x2(acc2[i][j], a2, b2[j]);
            }
        }
        __syncthreads();
    }

    #pragma unroll
    for (int i = 0; i < 8; i++) {
        int m = bm + ty * 8 + i;
        size_t orow;
        if (EPI == 2) orow = (size_t)scat_row(m) * C_DIM;
        else          orow = (size_t)m * N;
        #pragma unroll
        for (int j = 0; j < 4; j++) {
            int n0 = bn + tx * 8 + j * 2;
            float c0, c1;
            unpack_f32x2(acc2[i][j], c0, c1);
            float v0 = c0 + bias[n0];
            float v1 = c1 + bias[n0 + 1];
            if (EPI == 0) {
                C[orow + n0] = v0;         C[orow + n0 + 1] = v1;
            } else if (EPI == 1) {
                C[orow + n0] = gelu_f(v0); C[orow + n0 + 1] = gelu_f(v1);
            } else {
                C[orow + n0]     = res[orow + n0]     + v0;
                C[orow + n0 + 1] = res[orow + n0 + 1] + v1;
            }
        }
    }
}

// ---------------- reference-token projection ----------------
__global__ void __launch_bounds__(256) k_ref(const float* __restrict__ xr,
                                             const float* __restrict__ W,
                                             const float* __restrict__ bias,
                                             const float* __restrict__ dmu,
                                             const float* __restrict__ dls) {
    __shared__ float xs[C_DIM];
    int rb = blockIdx.x / NREF, r = blockIdx.x % NREF;
    int tid = threadIdx.x;
    const float* src = xr + (size_t)(rb * NREF + r) * C_DIM;
    xs[tid] = src[tid];
    xs[tid + 256] = src[tid + 256];
    __syncthreads();
    int lane = tid & 31, wrp = tid >> 5;
    for (int o = wrp; o < 1024; o += 8) {
        const float* wr = W + (size_t)o * C_DIM;
        float acc = 0.f;
        for (int k = lane; k < C_DIM; k += 32) acc += xs[k] * wr[k];
        #pragma unroll
        for (int s = 16; s > 0; s >>= 1) acc += __shfl_down_sync(0xffffffffu, acc, s);
        if (lane == 0) {
            acc += bias[o];
            int which = o >> 9, c = o & 511;
            int h = c >> 5, d = c & 31;
            size_t dst = ((size_t)(rb * HEADS + h) * NREF + r) * HD + d;
            if (which == 0) g_refq[dst] = dmu[c] + expf(dls[c]) * acc;
            else            g_refv[dst] = acc;
        }
    }
}

// ---------------- ra = q @ ref_q^T, written in conv layout ----------------
__global__ void __launch_bounds__(256) k_ra() {
    int w = blockIdx.x >> 4, h = blockIdx.x & 15;
    int bi = w / NW_PER, wl = w % NW_PER;
    __shared__ __align__(16) float Qs[NWIN * HD];
    __shared__ __align__(16) float Rs[NREF * 34];   // even stride (8B-aligned pairs)
    int tid = threadIdx.x;
    for (int idx = tid; idx < NWIN * HD; idx += 256) {
        int n = idx >> 5, d = idx & 31;
        Qs[idx] = g_qkv[(size_t)(w * NWIN + n) * 1536 + h * HD + d];
    }
    for (int idx = tid; idx < NREF * HD; idx += 256) {
        int r = idx >> 5, d = idx & 31;
        Rs[r * 34 + d] = g_refq[(size_t)(bi * HEADS + h) * NREF * HD + idx];
    }
    __syncthreads();
    size_t obase = ((size_t)(bi * HEADS + h) * CONV_H + wl * NWIN) * CONV_W;
    for (int o = tid; o < NWIN * NREF; o += 256) {
        int n = o / NREF, r = o % NREF;
        const ull* qp = (const ull*)&Qs[n * HD];
        const ull* rp = (const ull*)&Rs[r * 34];
        ull a2 = 0ull;
        #pragma unroll
        for (int k2 = 0; k2 < HD / 2; k2++) fma_f32x2(a2, qp[k2], rp[k2]);
        float lo, hi;
        unpack_f32x2(a2, lo, hi);
        g_ra[obase + (size_t)n * CONV_W + r] = lo + hi;
    }
}

// ---------------- 3x3 conv (16->16 channels) over (CONV_H, CONV_W) image ----------------
#define CTH 16
#define CTW 25
__global__ void __launch_bounds__(256) k_conv(const float* __restrict__ cw,
                                              const float* __restrict__ cb) {
    __shared__ float ins[16][CTH + 2][CTW + 2];            // 7776 floats
    __shared__ __align__(16) float ws2[144][16];           // 2304 floats
    int tid = threadIdx.x;
    int b  = blockIdx.z;
    int y0 = blockIdx.y * CTH;
    int x0 = blockIdx.x * CTW;
    for (int idx = tid; idx < 2304; idx += 256) {
        int o = idx / 144, rem = idx % 144;       // cw layout: o*144 + i*9 + kk
        ws2[rem][o] = cw[idx];
    }
    const int TILE = (CTH + 2) * (CTW + 2);
    for (int idx = tid; idx < 16 * TILE; idx += 256) {
        int ci = idx / TILE, rem = idx % TILE;
        int ly = rem / (CTW + 2), lx = rem % (CTW + 2);
        int gy = y0 - 1 + ly, gx = x0 - 1 + lx;
        float v = 0.f;
        if (gy >= 0 && gy < CONV_H && gx >= 0 && gx < CONV_W)
            v = g_ra[((size_t)(b * HEADS + ci) * CONV_H + gy) * CONV_W + gx];
        ins[ci][ly][lx] = v;
    }
    __syncthreads();
    int p0 = tid, p1 = tid + 256;
    int py0 = p0 / CTW, px0 = p0 % CTW;
    int py1 = p1 / CTW, px1 = p1 % CTW;
    bool has1 = (p1 < CTH * CTW);
    ull acc0[8], acc1[8];
    #pragma unroll
    for (int o2 = 0; o2 < 8; o2++) {
        ull init = pack_f32x2(cb[o2 * 2], cb[o2 * 2 + 1]);
        acc0[o2] = init; acc1[o2] = init;
    }
    for (int i = 0; i < 16; i++) {
        #pragma unroll
        for (int kk = 0; kk < 9; kk++) {
            int ky = kk / 3, kx = kk % 3;
            ull v0d = dup_f32x2(ins[i][py0 + ky][px0 + kx]);
            ull v1d = dup_f32x2(has1 ? ins[i][py1 + ky][px1 + kx] : 0.f);
            const ull* wp = (const ull*)ws2[i * 9 + kk];   // row is 64B-aligned
            #pragma unroll
            for (int o2 = 0; o2 < 8; o2++) {
                ull wv = wp[o2];
                fma_f32x2(acc0[o2], v0d, wv);
                fma_f32x2(acc1[o2], v1d, wv);
            }
        }
    }
    int gy0 = y0 + py0, gx0 = x0 + px0;
    #pragma unroll
    for (int o2 = 0; o2 < 8; o2++) {
        float lo, hi;
        unpack_f32x2(acc0[o2], lo, hi);
        g_u[((size_t)(b * HEADS + o2 * 2)     * CONV_H + gy0) * CONV_W + gx0] = lo;
        g_u[((size_t)(b * HEADS + o2 * 2 + 1) * CONV_H + gy0) * CONV_W + gx0] = hi;
    }
    if (has1) {
        int gy1 = y0 + py1, gx1 = x0 + px1;
        #pragma unroll
        for (int o2 = 0; o2 < 8; o2++) {
            float lo, hi;
            unpack_f32x2(acc1[o2], lo, hi);
            g_u[((size_t)(b * HEADS + o2 * 2)     * CONV_H + gy1) * CONV_W + gx1] = lo;
            g_u[((size_t)(b * HEADS + o2 * 2 + 1) * CONV_H + gy1) * CONV_W + gx1] = hi;
        }
    }
}

__global__ void k_zero_stats() {
    if (threadIdx.x < 64) g_stats[threadIdx.x] = 0.0;
}

// global sum/sumsq per (b,h), float4-vectorized
__global__ void __launch_bounds__(256) k_red() {
    int bh = blockIdx.y;
    const float4* base = (const float4*)&g_u[(size_t)bh * CONV_HW];
    int tid = threadIdx.x;
    float s = 0.f, s2 = 0.f;
    const int N4 = CONV_HW / 4;
    for (int i = blockIdx.x * 256 + tid; i < N4; i += gridDim.x * 256) {
        float4 v = base[i];
        s  += v.x + v.y + v.z + v.w;
        s2 += v.x * v.x + v.y * v.y + v.z * v.z + v.w * v.w;
    }
    __shared__ float rs[8], rs2[8];
    #pragma unroll
    for (int o = 16; o > 0; o >>= 1) {
        s  += __shfl_down_sync(0xffffffffu, s,  o);
        s2 += __shfl_down_sync(0xffffffffu, s2, o);
    }
    int lane = tid & 31, wid = tid >> 5;
    if (lane == 0) { rs[wid] = s; rs2[wid] = s2; }
    __syncthreads();
    if (tid == 0) {
        double S = 0.0, S2 = 0.0;
        #pragma unroll
        for (int k = 0; k < 8; k++) { S += (double)rs[k]; S2 += (double)rs2[k]; }
        atomicAdd(&g_stats[bh * 2],     S);
        atomicAdd(&g_stats[bh * 2 + 1], S2);
    }
}

// finalize stats ONCE per (b,h): the only fp64 in the whole pipeline now
__global__ void k_stat() {
    int i = threadIdx.x;
    if (i < 32) {
        double cnt = (double)CONV_HW;
        double mu  = g_stats[i * 2] / cnt;
        double var = g_stats[i * 2 + 1] / cnt - mu * mu;
        g_mu[i]  = (float)mu;
        g_inv[i] = rsqrtf((float)var + 1e-5f);
    }
}

// ra += gelu((u - mu) * inv)   — pure fp32, float4 streaming
__global__ void __launch_bounds__(256) k_fin() {
    size_t i4 = ((size_t)blockIdx.x * 256 + threadIdx.x) * 4;
    int bh = (int)(i4 / CONV_HW);          // CONV_HW % 4 == 0, no straddle
    float mu = g_mu[bh], inv = g_inv[bh];
    float4 u  = *(const float4*)&g_u[i4];
    float4 ra = *(float4*)&g_ra[i4];
    ra.x += gelu_f((u.x - mu) * inv);
    ra.y += gelu_f((u.y - mu) * inv);
    ra.z += gelu_f((u.z - mu) * inv);
    ra.w += gelu_f((u.w - mu) * inv);
    *(float4*)&g_ra[i4] = ra;
}

// ---------------- softmax over NREF + q_new = P @ ref_v * SCALE ----------------
// Fuses the LAST conv round's finalize: Ps = ra + gelu((u - mu) * inv)
__global__ void __launch_bounds__(256) k_softq() {
    int w = blockIdx.x >> 4, h = blockIdx.x & 15;
    int bi = w / NW_PER, wl = w % NW_PER;
    __shared__ float Ps[NWIN * NREF];   // 4900
    __shared__ float Vs[NREF * HD];     // 3200
    int tid = threadIdx.x;
    int bh = bi * HEADS + h;
    float muv = g_mu[bh], invv = g_inv[bh];
    size_t rbase = ((size_t)bh * CONV_H + wl * NWIN) * CONV_W;
    for (int idx = tid; idx < NWIN * NREF; idx += 256) {
        float uu = g_u[rbase + idx];
        Ps[idx] = g_ra[rbase + idx] + gelu_f((uu - muv) * invv);
    }
    for (int idx = tid; idx < NREF * HD; idx += 256)
        Vs[idx] = g_refv[(size_t)bh * NREF * HD + idx];
    __syncthreads();
    int lane = tid & 31, wrp = tid >> 5;
    for (int n = wrp; n < NWIN; n += 8) {
        float* row = Ps + n * NREF;
        float m = -3.4e38f;
        for (int r = lane; r < NREF; r += 32) m = fmaxf(m, row[r]);
        #pragma unroll
        for (int o = 16; o > 0; o >>= 1) m = fmaxf(m, __shfl_xor_sync(0xffffffffu, m, o));
        float s = 0.f;
        for (int r = lane; r < NREF; r += 32) { float e = __expf(row[r] - m); row[r] = e; s += e; }
        #pragma unroll
        for (int o = 16; o > 0; o >>= 1) s += __shfl_xor_sync(0xffffffffu, s, o);
        float inv = 1.f / s;
        for (int r = lane; r < NREF; r += 32) row[r] *= inv;
    }
    __syncthreads();
    for (int o = tid; o < NWIN * HD; o += 256) {
        int n = o >> 5, d = o & 31;
        float acc = 0.f;
        #pragma unroll 4
        for (int r = 0; r < NREF; r++) acc += Ps[n * NREF + r] * Vs[r * HD + d];
        g_qnew[((size_t)(w * HEADS + h) * NWIN + n) * HD + d] = acc * SCALE_ATT;
    }
}

// ---------------- windowed attention: S = q_new k^T + rpb + mask, softmax, @v ----------------
__global__ void __launch_bounds__(256) k_attn(const float* __restrict__ rpb,
                                              const float* __restrict__ mask) {
    int w = blockIdx.x >> 4, h = blockIdx.x & 15;
    int wl = w % NW_PER;
    __shared__ float Qs[NWIN * HD];
    __shared__ float Ks[NWIN * 33];   // padded
    __shared__ float Vs[NWIN * HD];
    __shared__ float Ss[NWIN * 50];
    int tid = threadIdx.x;
    for (int idx = tid; idx < NWIN * HD; idx += 256) {
        int n = idx >> 5, d = idx & 31;
        size_t base = (size_t)(w * NWIN + n) * 1536 + h * HD + d;
        Qs[idx]         = g_qnew[((size_t)(w * HEADS + h) * NWIN + n) * HD + d];
        Ks[n * 33 + d]  = g_qkv[base + 512];
        Vs[idx]         = g_qkv[base + 1024];
    }
    __syncthreads();
    for (int o = tid; o < NWIN * NWIN; o += 256) {
        int n = o / NWIN, m = o % NWIN;
        float acc = 0.f;
        #pragma unroll
        for (int k = 0; k < HD; k++) acc += Qs[n * HD + k] * Ks[m * 33 + k];
        int i1 = n / 7, j1 = n % 7, i2 = m / 7, j2 = m % 7;
        acc += rpb[((i1 - i2 + 6) * 13 + (j1 - j2 + 6)) * HEADS + h];
        acc += mask[((size_t)wl * NWIN + n) * NWIN + m];
        Ss[n * 50 + m] = acc;
    }
    __syncthreads();
    int lane = tid & 31, wrp = tid >> 5;
    for (int n = wrp; n < NWIN; n += 8) {
        float* row = Ss + n * 50;
        float m = -3.4e38f;
        for (int r = lane; r < NWIN; r += 32) m = fmaxf(m, row[r]);
        #pragma unroll
        for (int o = 16; o > 0; o >>= 1) m = fmaxf(m, __shfl_xor_sync(0xffffffffu, m, o));
        float s = 0.f;
        for (int r = lane; r < NWIN; r += 32) { float e = __expf(row[r] - m); row[r] = e; s += e; }
        #pragma unroll
        for (int o = 16; o > 0; o >>= 1) s += __shfl_xor_sync(0xffffffffu, s, o);
        float inv = 1.f / s;
        for (int r = lane; r < NWIN; r += 32) row[r] *= inv;
    }
    __syncthreads();
    for (int o = tid; o < NWIN * HD; o += 256) {
        int n = o >> 5, d = o & 31;
        float acc = 0.f;
        #pragma unroll 7
        for (int m = 0; m < NWIN; m++) acc += Ss[n * 50 + m] * Vs[m * HD + d];
        g_attno[(size_t)(w * NWIN + n) * C_DIM + h * HD + d] = acc;
    }
}

// ---------------- launch ----------------
extern "C" void kernel_launch(void* const* d_in, const int* in_sizes, int n_in,
                              void* d_out, int out_size) {
    (void)in_sizes; (void)n_in; (void)out_size;
    const float* x     = (const float*)d_in[0];
    const float* x_ref = (const float*)d_in[1];
    const float* mask  = (const float*)d_in[2];
    const float* n1w   = (const float*)d_in[3];
    const float* n1b   = (const float*)d_in[4];
    const float* qkvw  = (const float*)d_in[5];
    const float* qkvb  = (const float*)d_in[6];
    const float* dmu   = (const float*)d_in[7];
    const float* dls   = (const float*)d_in[8];
    const float* rpb   = (const float*)d_in[9];
    const float* rqw   = (const float*)d_in[10];
    const float* rqb   = (const float*)d_in[11];
    const float* cw    = (const float*)d_in[12];
    const float* cb    = (const float*)d_in[13];
    const float* pw    = (const float*)d_in[14];
    const float* pb    = (const float*)d_in[15];
    const float* n2w   = (const float*)d_in[16];
    const float* n2b   = (const float*)d_in[17];
    const float* f1w   = (const float*)d_in[18];
    const float* f1b   = (const float*)d_in[19];
    const float* f2w   = (const float*)d_in[20];
    const float* f2b   = (const float*)d_in[21];
    float* out = (float*)d_out;

    float *p_xw, *p_qkv, *p_attno, *p_y, *p_h2, *p_mlp;
    cudaGetSymbolAddress((void**)&p_xw,    g_xw);
    cudaGetSymbolAddress((void**)&p_qkv,   g_qkv);
    cudaGetSymbolAddress((void**)&p_attno, g_attno);
    cudaGetSymbolAddress((void**)&p_y,     g_y);
    cudaGetSymbolAddress((void**)&p_h2,    g_h2);
    cudaGetSymbolAddress((void**)&p_mlp,   g_mlp);

    // 1) LN1 + cyclic shift + window partition
    k_ln<true><<<NTOK, 256>>>(x, n1w, n1b, p_xw);
    // 2) qkv GEMM (25088 x 1536 x 512)
    k_gemm<0><<<dim3(1536 / BN, NTOK / BM), 256>>>(p_xw, qkvw, qkvb, p_qkv,
                                                   NTOK, 1536, C_DIM, nullptr);
    // 3) reference tokens -> ref_q / ref_v
    k_ref<<<B_IMG * NREF, 256>>>(x_ref, rqw, rqb, dmu, dls);
    // 4) ra = q @ ref_q^T (conv layout)
    k_ra<<<B_IMG * NW_PER * HEADS, 256>>>();
    // 5) 3 rounds of conv diffusion + global LN + gelu + residual
    //    (last round's finalize is fused into k_softq)
    for (int r = 0; r < 3; r++) {
        k_zero_stats<<<1, 64>>>();
        k_conv<<<dim3(CONV_W / CTW, CONV_H / CTH, B_IMG), 256>>>(cw, cb);
        k_red<<<dim3(48, 32), 256>>>();
        k_stat<<<1, 32>>>();
        if (r < 2)
            k_fin<<<(unsigned)(RA_TOTAL / 1024), 256>>>();
    }
    // 6) fused finalize + softmax(ra) @ ref_v * scale
    k_softq<<<B_IMG * NW_PER * HEADS, 256>>>();
    // 7) windowed attention
    k_attn<<<B_IMG * NW_PER * HEADS, 256>>>(rpb, mask);
    // 8) proj GEMM + window-reverse scatter + residual with x  -> y
    k_gemm<2><<<dim3(C_DIM / BN, NTOK / BM), 256>>>(p_attno, pw, pb, p_y,
                                                    NTOK, C_DIM, C_DIM, x);
    // 9) LN2
    k_ln<false><<<NTOK, 256>>>(p_y, n2w, n2b, p_h2);
    // 10) fc1 + gelu
    k_gemm<1><<<dim3(2048 / BN, NTOK / BM), 256>>>(p_h2, f1w, f1b, p_mlp,
                                                   NTOK, 2048, C_DIM, nullptr);
    // 11) fc2 + residual with y -> out
    k_gemm<3><<<dim3(C_DIM / BN, NTOK / BM), 256>>>(p_mlp, f2w, f2b, out,
                                                    NTOK, C_DIM, 2048, p_y);
}